// round 5
// baseline (speedup 1.0000x reference)
#include <cuda_runtime.h>
#include <math.h>

#define BB 64
#define LL 2048
#define DD 256
#define KK 32
#define NCHUNK 8
#define CHUNK 256          // LL / NCHUNK
#define ST 64              // subtile rows
#define NSUB 4             // CHUNK / ST
#define NTH 256
#define XPAD 260           // 260 % 32 == 4 -> conflict-free patterns used below
#define WPAD 33
#define PPAD 33

// Scratch (no allocations allowed): flash partials per (batch, chunk)
__device__ float g_partC[BB * NCHUNK * KK * DD];   // 16 MB
__device__ float g_partM[BB * NCHUNK * KK];
__device__ float g_partS[BB * NCHUNK * KK];

__global__ __launch_bounds__(NTH, 2)
void fused_kernel(const float* __restrict__ X, const float* __restrict__ W) {
    extern __shared__ float smem[];
    float* Wt = smem;                  // [DD][WPAD]  W transposed: Wt[d*33 + k]
    float* Xs = Wt + DD * WPAD;        // [ST][XPAD]
    float* Ps = Xs + ST * XPAD;        // [ST][PPAD]  scores -> probs
    __shared__ float Sm[KK], Ss[KK], Sf[KK];

    const int b = blockIdx.y, c = blockIdx.x;
    const int t = threadIdx.x;
    const int lane = t & 31, w = t >> 5;
    const int kq = lane & 7, rr = lane >> 3;
    const int w4 = w * 4;

    // Stage W transposed (coalesced LDG, conflict-free STS via pad 33)
    for (int i = t; i < KK * DD; i += NTH) {
        int k = i >> 8, d = i & 255;
        Wt[d * WPAD + k] = W[i];
    }
    if (t < KK) { Sm[t] = -INFINITY; Ss[t] = 0.f; }

    // Accumulators: thread owns codes k = w4..w4+3, dims d = lane + 32*j
    float C[4][8];
    #pragma unroll
    for (int i = 0; i < 4; i++)
        #pragma unroll
        for (int j = 0; j < 8; j++) C[i][j] = 0.f;

    const int row0 = c * CHUNK;

    for (int sub = 0; sub < NSUB; sub++) {
        __syncthreads();   // previous accumulate finished reading Xs/Ps
        // ---- stage X subtile (64 x 256 fp32) with float4 ----
        {
            const float4* src = (const float4*)(X + ((size_t)b * LL + row0 + sub * ST) * DD);
            float4* dst = (float4*)Xs;
            #pragma unroll
            for (int i = t; i < ST * DD / 4; i += NTH) {
                int l = i >> 6, cpos = i & 63;
                dst[l * (XPAD / 4) + cpos] = src[i];
            }
        }
        __syncthreads();
        // ---- scoring: thread computes S[l0..l0+1][kq*4..kq*4+3] ----
        {
            const int l0 = w * 8 + rr * 2;
            float s0[4] = {0.f, 0.f, 0.f, 0.f};
            float s1[4] = {0.f, 0.f, 0.f, 0.f};
            const float* xr = Xs + l0 * XPAD;
            const float* Wc = Wt + kq * 4;
            #pragma unroll 4
            for (int d = 0; d < DD; d++) {
                float x0 = xr[d], x1 = xr[XPAD + d];
                const float* wrow = Wc + (size_t)d * WPAD;
                #pragma unroll
                for (int i = 0; i < 4; i++) {
                    float wv = wrow[i];
                    s0[i] += x0 * wv;
                    s1[i] += x1 * wv;
                }
            }
            #pragma unroll
            for (int i = 0; i < 4; i++) {
                Ps[l0 * PPAD + kq * 4 + i]       = s0[i];
                Ps[(l0 + 1) * PPAD + kq * 4 + i] = s1[i];
            }
        }
        __syncthreads();
        // ---- online softmax update: warp w owns codes w4..w4+3, lanes span rows ----
        {
            #pragma unroll
            for (int i = 0; i < 4; i++) {
                int k = w4 + i;
                float v0 = Ps[lane * PPAD + k];
                float v1 = Ps[(lane + 32) * PPAD + k];
                float mx = fmaxf(v0, v1);
                #pragma unroll
                for (int off = 16; off > 0; off >>= 1)
                    mx = fmaxf(mx, __shfl_xor_sync(0xffffffffu, mx, off));
                float mold = Sm[k];
                float mnew = fmaxf(mold, mx);
                float p0 = __expf(v0 - mnew), p1 = __expf(v1 - mnew);
                Ps[lane * PPAD + k]        = p0;
                Ps[(lane + 32) * PPAD + k] = p1;
                float sm = p0 + p1;
                #pragma unroll
                for (int off = 16; off > 0; off >>= 1)
                    sm += __shfl_xor_sync(0xffffffffu, sm, off);
                if (lane == 0) {
                    float f = __expf(mold - mnew);   // exp(-inf)=0 on first subtile
                    Sf[k] = f;
                    Ss[k] = Ss[k] * f + sm;
                    Sm[k] = mnew;
                }
            }
        }
        __syncthreads();
        // ---- rescale + accumulate ----
        {
            float f0 = Sf[w4], f1 = Sf[w4 + 1], f2 = Sf[w4 + 2], f3 = Sf[w4 + 3];
            #pragma unroll
            for (int j = 0; j < 8; j++) {
                C[0][j] *= f0; C[1][j] *= f1; C[2][j] *= f2; C[3][j] *= f3;
            }
            #pragma unroll 2
            for (int l = 0; l < ST; l++) {
                float p0 = Ps[l * PPAD + w4];
                float p1 = Ps[l * PPAD + w4 + 1];
                float p2 = Ps[l * PPAD + w4 + 2];
                float p3 = Ps[l * PPAD + w4 + 3];
                const float* xr = Xs + l * XPAD + lane;
                #pragma unroll
                for (int j = 0; j < 8; j++) {
                    float xv = xr[j * 32];
                    C[0][j] += p0 * xv;
                    C[1][j] += p1 * xv;
                    C[2][j] += p2 * xv;
                    C[3][j] += p3 * xv;
                }
            }
        }
    }
    __syncthreads();
    // ---- write partials ----
    {
        float* Co = g_partC + ((size_t)(b * NCHUNK + c) * KK) * DD;
        #pragma unroll
        for (int i = 0; i < 4; i++)
            #pragma unroll
            for (int j = 0; j < 8; j++)
                Co[(w4 + i) * DD + lane + 32 * j] = C[i][j];
        if (t < KK) {
            g_partM[(b * NCHUNK + c) * KK + t] = Sm[t];
            g_partS[(b * NCHUNK + c) * KK + t] = Ss[t];
        }
    }
}

// Combine 8 chunk-partials per (b, k): C = sum_c C_c * exp(m_c - M) / S
__global__ void combine_kernel(float* __restrict__ out) {
    const int bk = blockIdx.x;
    const int b = bk >> 5, k = bk & 31;
    const int d = threadIdx.x;
    float mc[NCHUNK], sc[NCHUNK];
    float M = -INFINITY;
    #pragma unroll
    for (int c = 0; c < NCHUNK; c++) {
        mc[c] = g_partM[(b * NCHUNK + c) * KK + k];
        M = fmaxf(M, mc[c]);
    }
    float S = 0.f;
    #pragma unroll
    for (int c = 0; c < NCHUNK; c++) {
        sc[c] = __expf(mc[c] - M);
        S += g_partS[(b * NCHUNK + c) * KK + k] * sc[c];
    }
    float inv = 1.f / S;
    float acc = 0.f;
    #pragma unroll
    for (int c = 0; c < NCHUNK; c++)
        acc += g_partC[((size_t)(b * NCHUNK + c) * KK + k) * DD + d] * sc[c];
    out[((size_t)b * KK + k) * DD + d] = acc * inv;
}

extern "C" void kernel_launch(void* const* d_in, const int* in_sizes, int n_in,
                              void* d_out, int out_size) {
    const float* X = (const float*)d_in[0];   // rev_repr (64, 2048, 256) f32
    const float* W = (const float*)d_in[1];   // W_codes  (32, 256) f32
    float* out = (float*)d_out;               // contexts (64, 32, 256) f32

    const int smem_bytes = (DD * WPAD + ST * XPAD + ST * PPAD) * (int)sizeof(float); // ~106 KB
    cudaFuncSetAttribute(fused_kernel, cudaFuncAttributeMaxDynamicSharedMemorySize, smem_bytes);

    dim3 grid(NCHUNK, BB);
    fused_kernel<<<grid, NTH, smem_bytes>>>(X, W);
    combine_kernel<<<BB * KK, DD>>>(out);
}

// round 11
// speedup vs baseline: 2.3546x; 2.3546x over previous
#include <cuda_runtime.h>
#include <cuda_bf16.h>
#include <cstdint>
#include <math.h>

#define BB 64
#define LL 2048
#define DD 256
#define KK 32
#define NCHUNK 2
#define CHUNK 1024
#define ST 128
#define NSUB 8
#define NTH 256

// bf16 element strides (padded: +8 elems -> ldmatrix phases conflict-free)
#define XSTR 264            // X rows: 528 B stride (528/4 = 132 = 4 mod 32)
#define WSTR 264            // W rows: 528 B
#define PSTR 40             // P rows: 80 B  (80/4 = 20 mod 32)

// smem byte offsets
#define XHI 0               // [128][264] bf16 = 67584 B
#define XLO 67584
#define WSM 135168          // [64][264] bf16: rows 0-31 Whi, 32-63 Wlo = 33792 B
#define PHI 168960          // [128][40] bf16 = 10240 B
#define PLO 179200
#define SSUM 189440         // 32 floats
#define SMEM_BYTES (SSUM + 128)

__device__ float g_partC[BB * NCHUNK * KK * DD];   // 4 MB
__device__ float g_partS[BB * NCHUNK * KK];

__device__ __forceinline__ uint32_t s2u(const void* p) {
    uint32_t a;
    asm("{ .reg .u64 t; cvta.to.shared.u64 t, %1; cvt.u32.u64 %0, t; }" : "=r"(a) : "l"(p));
    return a;
}
__device__ __forceinline__ uint32_t pk(__nv_bfloat16 a, __nv_bfloat16 b) {
    return (uint32_t)__bfloat16_as_ushort(a) | ((uint32_t)__bfloat16_as_ushort(b) << 16);
}

#define LDSM4(r, a) \
    asm volatile("ldmatrix.sync.aligned.m8n8.x4.shared.b16 {%0,%1,%2,%3}, [%4];" \
        : "=r"((r)[0]), "=r"((r)[1]), "=r"((r)[2]), "=r"((r)[3]) : "r"(a))
#define LDSM4T(r, a) \
    asm volatile("ldmatrix.sync.aligned.m8n8.x4.trans.shared.b16 {%0,%1,%2,%3}, [%4];" \
        : "=r"((r)[0]), "=r"((r)[1]), "=r"((r)[2]), "=r"((r)[3]) : "r"(a))
#define LDSM2(r, a) \
    asm volatile("ldmatrix.sync.aligned.m8n8.x2.shared.b16 {%0,%1}, [%2];" \
        : "=r"((r)[0]), "=r"((r)[1]) : "r"(a))
// D += A @ B : A 16x16 row, B 16x8 col, fp32 accum
#define MMA(c, a, b0, b1) \
    asm volatile("mma.sync.aligned.m16n8k16.row.col.f32.bf16.bf16.f32 " \
        "{%0,%1,%2,%3}, {%4,%5,%6,%7}, {%8,%9}, {%0,%1,%2,%3};" \
        : "+f"((c)[0]), "+f"((c)[1]), "+f"((c)[2]), "+f"((c)[3]) \
        : "r"((a)[0]), "r"((a)[1]), "r"((a)[2]), "r"((a)[3]), "r"(b0), "r"(b1))

__global__ __launch_bounds__(NTH, 1)
void fused_kernel(const float* __restrict__ X, const float* __restrict__ W) {
    extern __shared__ __align__(128) char smem[];
    const uint32_t sb = s2u(smem);
    float* Ssum = (float*)(smem + SSUM);

    const int t = threadIdx.x, lane = t & 31, w = t >> 5;
    const int g = lane >> 2, tid4 = lane & 3;
    const int cchunk = blockIdx.x, b = blockIdx.y;

    // ---- W -> Whi/Wlo bf16 (once) ----
    for (int i = t; i < KK * DD; i += NTH) {
        int k = i >> 8, d = i & 255;
        float v = W[i];
        __nv_bfloat16 hi = __float2bfloat16(v);
        __nv_bfloat16 lo = __float2bfloat16(v - __bfloat162float(hi));
        *(__nv_bfloat16*)(smem + WSM + (k * WSTR + d) * 2)          = hi;
        *(__nv_bfloat16*)(smem + WSM + ((k + 32) * WSTR + d) * 2)   = lo;
    }
    if (t < KK) Ssum[t] = 0.f;

    // ---- per-thread ldmatrix address components ----
    // GEMM1 A (X, non-trans x4): m0 rows, m1 rows+8, m2 cols+8, m3 both
    const uint32_t a1_off = (uint32_t)((w * 16 + (lane & 7) + ((lane >> 3) & 1) * 8) * (XSTR * 2)
                                       + ((lane >> 4) & 1) * 16);
    // GEMM1 B (W, x2): lanes 0-7 -> m0 (cols d0..7), 8-15 -> m1 (cols d0+8..15)
    const uint32_t b1_row = (uint32_t)(lane & 7);
    const uint32_t b1_colb = (uint32_t)(((lane >> 3) & 1) * 16);
    // GEMM2 A (X^T via trans x4): m1 = cols+8, m2 = rows+8
    const uint32_t a2_row = (uint32_t)((lane & 7) + ((lane >> 4) & 1) * 8);
    const uint32_t a2_colb = (uint32_t)((w * 32 + ((lane >> 3) & 1) * 8) * 2);
    // GEMM2 B (P^T via trans x4): m1 = rows+8, m2 = cols+8
    const uint32_t b2_row = (uint32_t)((lane & 7) + ((lane >> 3) & 1) * 8);
    const uint32_t b2_colb = (uint32_t)(((lane >> 4) & 1) * 16);

    float Cacc[2][4][4];
    #pragma unroll
    for (int m = 0; m < 2; m++)
        #pragma unroll
        for (int n = 0; n < 4; n++)
            #pragma unroll
            for (int j = 0; j < 4; j++) Cacc[m][n][j] = 0.f;
    float Sacc[8];
    #pragma unroll
    for (int i = 0; i < 8; i++) Sacc[i] = 0.f;

    const float* Xg = X + ((size_t)b * LL + (size_t)cchunk * CHUNK) * DD;

    for (int sub = 0; sub < NSUB; sub++) {
        // ---- stage X subtile: f32 -> Xhi/Xlo bf16 ----
        {
            const float4* src = (const float4*)(Xg + (size_t)sub * ST * DD);
            #pragma unroll
            for (int i = t; i < ST * 32; i += NTH) {
                int row = i >> 5, cg = i & 31;
                float4 v0 = src[row * 64 + cg * 2];
                float4 v1 = src[row * 64 + cg * 2 + 1];
                __nv_bfloat16 h[8], lo[8];
                float f[8] = {v0.x, v0.y, v0.z, v0.w, v1.x, v1.y, v1.z, v1.w};
                #pragma unroll
                for (int e = 0; e < 8; e++) {
                    h[e]  = __float2bfloat16(f[e]);
                    lo[e] = __float2bfloat16(f[e] - __bfloat162float(h[e]));
                }
                uint32_t off = (uint32_t)(row * (XSTR * 2) + cg * 16);
                *(uint4*)(smem + XHI + off) = make_uint4(pk(h[0],h[1]), pk(h[2],h[3]),
                                                        pk(h[4],h[5]), pk(h[6],h[7]));
                *(uint4*)(smem + XLO + off) = make_uint4(pk(lo[0],lo[1]), pk(lo[2],lo[3]),
                                                        pk(lo[4],lo[5]), pk(lo[6],lo[7]));
            }
        }
        __syncthreads();

        // ---- GEMM1: D1[16 l rows of warp][32 codes] = X @ W^T (3-term split) ----
        float d1[4][4];
        #pragma unroll
        for (int n = 0; n < 4; n++)
            #pragma unroll
            for (int j = 0; j < 4; j++) d1[n][j] = 0.f;
        #pragma unroll
        for (int ks = 0; ks < 16; ks++) {
            uint32_t Ah[4], Al[4], Bh[2], Bl[2];
            LDSM4(Ah, sb + XHI + a1_off + ks * 32);
            LDSM4(Al, sb + XLO + a1_off + ks * 32);
            #pragma unroll
            for (int nt = 0; nt < 4; nt++) {
                uint32_t wa = sb + WSM + (nt * 8 + b1_row) * (WSTR * 2) + b1_colb + ks * 32;
                LDSM2(Bh, wa);
                LDSM2(Bl, wa + 32 * (WSTR * 2));
                MMA(d1[nt], Ah, Bh[0], Bh[1]);
                MMA(d1[nt], Ah, Bl[0], Bl[1]);
                MMA(d1[nt], Al, Bh[0], Bh[1]);
            }
        }

        // ---- softmax numerators in-register; store P hi/lo [l][code] ----
        {
            const int r0 = w * 16 + g, r1 = r0 + 8;
            #pragma unroll
            for (int nt = 0; nt < 4; nt++) {
                float p0 = __expf(d1[nt][0]);
                float p1 = __expf(d1[nt][1]);
                float p2 = __expf(d1[nt][2]);
                float p3 = __expf(d1[nt][3]);
                Sacc[nt * 2]     += p0 + p2;
                Sacc[nt * 2 + 1] += p1 + p3;
                __nv_bfloat16 h0 = __float2bfloat16(p0), h1 = __float2bfloat16(p1);
                __nv_bfloat16 h2 = __float2bfloat16(p2), h3 = __float2bfloat16(p3);
                __nv_bfloat16 q0 = __float2bfloat16(p0 - __bfloat162float(h0));
                __nv_bfloat16 q1 = __float2bfloat16(p1 - __bfloat162float(h1));
                __nv_bfloat16 q2 = __float2bfloat16(p2 - __bfloat162float(h2));
                __nv_bfloat16 q3 = __float2bfloat16(p3 - __bfloat162float(h3));
                uint32_t o0 = (uint32_t)(r0 * (PSTR * 2) + (nt * 8 + 2 * tid4) * 2);
                uint32_t o1 = (uint32_t)(r1 * (PSTR * 2) + (nt * 8 + 2 * tid4) * 2);
                *(uint32_t*)(smem + PHI + o0) = pk(h0, h1);
                *(uint32_t*)(smem + PHI + o1) = pk(h2, h3);
                *(uint32_t*)(smem + PLO + o0) = pk(q0, q1);
                *(uint32_t*)(smem + PLO + o1) = pk(q2, q3);
            }
        }
        __syncthreads();

        // ---- GEMM2: C^T[32 d of warp][32 codes] += X^T @ P^T (3-term split) ----
        #pragma unroll
        for (int ks = 0; ks < 8; ks++) {
            const int l0 = ks * 16;
            uint32_t BPh[8], BPl[8];
            uint32_t pa = sb + PHI + (l0 + b2_row) * (PSTR * 2) + b2_colb;
            LDSM4T(BPh, pa);           // frags: codes 0-7 (b0,b1), codes 8-15 (b2,b3)
            LDSM4T(BPh + 4, pa + 32);  // codes 16-23, 24-31
            uint32_t pl = sb + PLO + (l0 + b2_row) * (PSTR * 2) + b2_colb;
            LDSM4T(BPl, pl);
            LDSM4T(BPl + 4, pl + 32);
            #pragma unroll
            for (int mt = 0; mt < 2; mt++) {
                uint32_t Ah[4], Al[4];
                uint32_t xa = (l0 + a2_row) * (XSTR * 2) + a2_colb + mt * 32;
                LDSM4T(Ah, sb + XHI + xa);
                LDSM4T(Al, sb + XLO + xa);
                #pragma unroll
                for (int nt = 0; nt < 4; nt++) {
                    MMA(Cacc[mt][nt], Ah, BPh[nt * 2], BPh[nt * 2 + 1]);
                    MMA(Cacc[mt][nt], Ah, BPl[nt * 2], BPl[nt * 2 + 1]);
                    MMA(Cacc[mt][nt], Al, BPh[nt * 2], BPh[nt * 2 + 1]);
                }
            }
        }
        __syncthreads();   // X/P free for next subtile
    }

    // ---- softmax denominators: reduce over row-lanes, atomic into Ssum ----
    #pragma unroll
    for (int i = 0; i < 8; i++) {
        float v = Sacc[i];
        v += __shfl_xor_sync(0xffffffffu, v, 4);
        v += __shfl_xor_sync(0xffffffffu, v, 8);
        v += __shfl_xor_sync(0xffffffffu, v, 16);
        Sacc[i] = v;
    }
    if (lane < 4) {
        #pragma unroll
        for (int nt = 0; nt < 4; nt++) {
            atomicAdd(&Ssum[nt * 8 + 2 * lane],     Sacc[nt * 2]);
            atomicAdd(&Ssum[nt * 8 + 2 * lane + 1], Sacc[nt * 2 + 1]);
        }
    }
    __syncthreads();

    // ---- write partials ----
    const int bc = b * NCHUNK + cchunk;
    float* Co = g_partC + (size_t)bc * KK * DD;
    #pragma unroll
    for (int mt = 0; mt < 2; mt++) {
        const int dr = w * 32 + mt * 16 + g;
        #pragma unroll
        for (int nt = 0; nt < 4; nt++) {
            const int c0 = nt * 8 + 2 * tid4;
            Co[(size_t)c0 * DD + dr]           = Cacc[mt][nt][0];
            Co[(size_t)(c0 + 1) * DD + dr]     = Cacc[mt][nt][1];
            Co[(size_t)c0 * DD + dr + 8]       = Cacc[mt][nt][2];
            Co[(size_t)(c0 + 1) * DD + dr + 8] = Cacc[mt][nt][3];
        }
    }
    if (t < KK) g_partS[bc * KK + t] = Ssum[t];
}

// out[b,k,d] = (C0[k,d] + C1[k,d]) / (S0[k] + S1[k])
__global__ void combine_kernel(float* __restrict__ out) {
    const int bk = blockIdx.x;
    const int b = bk >> 5, k = bk & 31;
    const int d = threadIdx.x;
    const float S = g_partS[(b * NCHUNK) * KK + k] + g_partS[(b * NCHUNK + 1) * KK + k];
    const float* C0 = g_partC + (size_t)(b * NCHUNK) * KK * DD;
    const float* C1 = g_partC + (size_t)(b * NCHUNK + 1) * KK * DD;
    float acc = C0[(size_t)k * DD + d] + C1[(size_t)k * DD + d];
    out[((size_t)b * KK + k) * DD + d] = acc / S;
}

extern "C" void kernel_launch(void* const* d_in, const int* in_sizes, int n_in,
                              void* d_out, int out_size) {
    const float* X = (const float*)d_in[0];   // rev_repr (64, 2048, 256) f32
    const float* W = (const float*)d_in[1];   // W_codes  (32, 256) f32
    float* out = (float*)d_out;               // contexts (64, 32, 256) f32

    cudaFuncSetAttribute(fused_kernel, cudaFuncAttributeMaxDynamicSharedMemorySize, SMEM_BYTES);
    dim3 grid(NCHUNK, BB);
    fused_kernel<<<grid, NTH, SMEM_BYTES>>>(X, W);
    combine_kernel<<<BB * KK, DD>>>(out);
}